// round 4
// baseline (speedup 1.0000x reference)
#include <cuda_runtime.h>
#include <cuda_bf16.h>
#include <math.h>

// Problem constants (from reference)
#define N_IN   100000
#define N_OUT  200000
#define C_IN   128
#define C_OUT  64
#define KOFF   27
#define MPAIRS 100000
#define BN_EPS 1e-5f

// Conv kernel tiling
#define WARPS_PER_BLOCK 8
#define PPW 8                               // pairs per warp per chunk
#define PAIRS_PER_CHUNK (WARPS_PER_BLOCK * PPW)   // 64
#define NCHUNKS ((MPAIRS + PAIRS_PER_CHUNK - 1) / PAIRS_PER_CHUNK)  // 1563
#define CONV_GRID_X 118
#define XPAD 132                            // x staging row stride (floats), bank-decorrelated

// BN stats scratch (no cudaMalloc allowed -> __device__ globals)
__device__ float g_sum[C_OUT];
__device__ float g_sq[C_OUT];
__device__ float g_scale[C_OUT];
__device__ float g_bias[C_OUT];

// ---- packed f32x2 helpers (sm_103a FFMA2 path) ------------------------------
__device__ __forceinline__ unsigned long long ffma2(
    unsigned long long a, unsigned long long b, unsigned long long c)
{
    unsigned long long d;
    asm("fma.rn.f32x2 %0, %1, %2, %3;" : "=l"(d) : "l"(a), "l"(b), "l"(c));
    return d;
}
__device__ __forceinline__ unsigned long long pack_dup(float v)
{
    unsigned long long d;
    asm("mov.b64 %0, {%1, %1};" : "=l"(d) : "f"(v));
    return d;
}

// ---------------------------------------------------------------------------
// Kernel 1: gather -> per-k GEMM (FFMA2) -> scatter-add (RED.v4) into out
// Block: 256 threads (8 warps). blockIdx.y = kernel offset k.
// Lane partition within a warp: lane = lg*8 + ll
//   ll (0..7)  owns output channels [8*ll, 8*ll+8)
//   lg (0..3)  owns pairs {2*lg, 2*lg+1}
// Each lane: 16 accumulators as 8 packed f32x2 regs.
// SMEM: wsh 128x64 f32 (32KB) + xsh 8 warps x 8 pairs x XPAD f32 (33.8KB)
// ---------------------------------------------------------------------------
__global__ void __launch_bounds__(256, 3) conv_kernel(
    const float* __restrict__ x,
    const float* __restrict__ weight,
    const int*   __restrict__ in_map,
    const int*   __restrict__ out_map,
    float*       __restrict__ out)
{
    extern __shared__ float smem[];
    float* wsh = smem;                        // 8192 floats
    float* xsh = smem + C_IN * C_OUT;         // 8 * 8 * XPAD floats

    const int k = blockIdx.y;

    // Load weight[k] into shared (vectorized)
    {
        const float4* src = (const float4*)(weight + (size_t)k * C_IN * C_OUT);
        float4* dst = (float4*)wsh;
        #pragma unroll 4
        for (int i = threadIdx.x; i < C_IN * C_OUT / 4; i += blockDim.x)
            dst[i] = src[i];
    }
    __syncthreads();

    const int warp = threadIdx.x >> 5;
    const int lane = threadIdx.x & 31;
    const int ll   = lane & 7;     // channel group
    const int lg   = lane >> 3;    // pair group
    float* xw = xsh + warp * (PPW * XPAD);

    for (int chunk = blockIdx.x; chunk < NCHUNKS; chunk += gridDim.x) {
        const int base = chunk * PAIRS_PER_CHUNK + warp * PPW;

        // Gather 8 x-rows into shared; each lane loads one float4 per row.
        int orow[PPW];
        #pragma unroll
        for (int p = 0; p < PPW; p++) {
            const int idx = base + p;
            if (idx < MPAIRS) {
                const int gi = k * MPAIRS + idx;
                const int ir = in_map[gi];
                orow[p] = out_map[gi];
                float4 v = ((const float4*)(x + (size_t)ir * C_IN))[lane];
                *(float4*)(xw + p * XPAD + 4 * lane) = v;
            } else {
                orow[p] = -1;
            }
        }
        __syncwarp();

        // Accumulators: acc0 for pair 2*lg, acc1 for pair 2*lg+1.
        // acc*[jj] packs channels (8*ll + 2*jj, 8*ll + 2*jj + 1).
        unsigned long long acc0[4], acc1[4];
        #pragma unroll
        for (int jj = 0; jj < 4; jj++) { acc0[jj] = 0ull; acc1[jj] = 0ull; }

        const float* xr0 = xw + (2 * lg + 0) * XPAD;
        const float* xr1 = xw + (2 * lg + 1) * XPAD;

        #pragma unroll 4
        for (int c4 = 0; c4 < C_IN / 4; c4++) {
            // 4 c_in at a time: vector-load x for both pairs (16B aligned rows).
            float4 xv0 = *(const float4*)(xr0 + 4 * c4);
            float4 xv1 = *(const float4*)(xr1 + 4 * c4);
            const float xs0[4] = {xv0.x, xv0.y, xv0.z, xv0.w};
            const float xs1[4] = {xv1.x, xv1.y, xv1.z, xv1.w};
            #pragma unroll
            for (int i = 0; i < 4; i++) {
                const int ci = 4 * c4 + i;
                unsigned long long xp0 = pack_dup(xs0[i]);
                unsigned long long xp1 = pack_dup(xs1[i]);
                const unsigned long long* wrow =
                    (const unsigned long long*)(wsh + ci * C_OUT + 8 * ll);
                #pragma unroll
                for (int jj = 0; jj < 4; jj++) {
                    unsigned long long w = wrow[jj];
                    acc0[jj] = ffma2(xp0, w, acc0[jj]);
                    acc1[jj] = ffma2(xp1, w, acc1[jj]);
                }
            }
        }

        // Scatter-add: for each of this lane's 2 pairs, write its 8 channels
        // as two 16B vector reductions.
        #pragma unroll
        for (int t = 0; t < 2; t++) {
            const int p = 2 * lg + t;
            const int r = orow[p];
            if (r >= 0) {
                const unsigned long long* a = t ? acc1 : acc0;
                float2 a0 = *(const float2*)&a[0];
                float2 a1 = *(const float2*)&a[1];
                float2 a2 = *(const float2*)&a[2];
                float2 a3 = *(const float2*)&a[3];
                float* dst = out + (size_t)r * C_OUT + 8 * ll;
                asm volatile("red.global.add.v4.f32 [%0], {%1, %2, %3, %4};"
                             :: "l"(dst), "f"(a0.x), "f"(a0.y), "f"(a1.x), "f"(a1.y)
                             : "memory");
                asm volatile("red.global.add.v4.f32 [%0], {%1, %2, %3, %4};"
                             :: "l"(dst + 4), "f"(a2.x), "f"(a2.y), "f"(a3.x), "f"(a3.y)
                             : "memory");
            }
        }
        __syncwarp();   // protect xw before next chunk's gather overwrites it
    }
}

// ---------------------------------------------------------------------------
// Kernel 2a: zero stats accumulators
// ---------------------------------------------------------------------------
__global__ void zero_stats_kernel() {
    if (threadIdx.x < C_OUT) { g_sum[threadIdx.x] = 0.f; g_sq[threadIdx.x] = 0.f; }
}

// ---------------------------------------------------------------------------
// Kernel 2b: per-channel sum / sumsq over [N_OUT, 64]
// ---------------------------------------------------------------------------
__global__ void stats_kernel(const float* __restrict__ out) {
    const int c    = threadIdx.x & 63;
    const int rsub = threadIdx.x >> 6;   // 0..3
    float s = 0.f, q = 0.f;
    for (int r = blockIdx.x * 4 + rsub; r < N_OUT; r += gridDim.x * 4) {
        float v = out[(size_t)r * C_OUT + c];
        s += v;
        q = fmaf(v, v, q);
    }
    __shared__ float ssh[256];
    __shared__ float qsh[256];
    ssh[threadIdx.x] = s;
    qsh[threadIdx.x] = q;
    __syncthreads();
    if (rsub == 0) {
        s = ssh[c] + ssh[c + 64] + ssh[c + 128] + ssh[c + 192];
        q = qsh[c] + qsh[c + 64] + qsh[c + 128] + qsh[c + 192];
        atomicAdd(&g_sum[c], s);
        atomicAdd(&g_sq[c], q);
    }
}

// ---------------------------------------------------------------------------
// Kernel 3: finalize BN affine params
// ---------------------------------------------------------------------------
__global__ void finalize_kernel(const float* __restrict__ gamma,
                                const float* __restrict__ beta) {
    const int c = threadIdx.x;
    if (c < C_OUT) {
        const float invn = 1.0f / (float)N_OUT;
        float mean = g_sum[c] * invn;
        float var  = g_sq[c] * invn - mean * mean;
        float sc   = gamma[c] * rsqrtf(var + BN_EPS);
        g_scale[c] = sc;
        g_bias[c]  = beta[c] - mean * sc;
    }
}

// ---------------------------------------------------------------------------
// Kernel 4: in-place normalize + ReLU, vectorized float4
// ---------------------------------------------------------------------------
__global__ void norm_kernel(float* __restrict__ out, long long n4) {
    long long i = (long long)blockIdx.x * blockDim.x + threadIdx.x;
    if (i < n4) {
        float4 v = ((float4*)out)[i];
        int c0 = (int)((i * 4) & 63);
        v.x = fmaxf(fmaf(v.x, g_scale[c0 + 0], g_bias[c0 + 0]), 0.f);
        v.y = fmaxf(fmaf(v.y, g_scale[c0 + 1], g_bias[c0 + 1]), 0.f);
        v.z = fmaxf(fmaf(v.z, g_scale[c0 + 2], g_bias[c0 + 2]), 0.f);
        v.w = fmaxf(fmaf(v.w, g_scale[c0 + 3], g_bias[c0 + 3]), 0.f);
        ((float4*)out)[i] = v;
    }
}

// ---------------------------------------------------------------------------
// kernel_launch — graph-capturable pipeline, default stream
// Inputs (metadata order): x, weight, gamma, beta, in_map, out_map
// ---------------------------------------------------------------------------
extern "C" void kernel_launch(void* const* d_in, const int* in_sizes, int n_in,
                              void* d_out, int out_size)
{
    const float* x       = (const float*)d_in[0];
    const float* weight  = (const float*)d_in[1];
    const float* gamma   = (const float*)d_in[2];
    const float* beta    = (const float*)d_in[3];
    const int*   in_map  = (const int*)d_in[4];
    const int*   out_map = (const int*)d_in[5];
    float*       out     = (float*)d_out;

    // Conv accumulates into d_out; it is poisoned, so zero it first.
    cudaMemsetAsync(out, 0, (size_t)out_size * sizeof(float));
    zero_stats_kernel<<<1, 64>>>();

    const int smem_bytes =
        (C_IN * C_OUT + WARPS_PER_BLOCK * PPW * XPAD) * (int)sizeof(float);
    cudaFuncSetAttribute(conv_kernel, cudaFuncAttributeMaxDynamicSharedMemorySize, smem_bytes);

    dim3 cgrid(CONV_GRID_X, KOFF);
    conv_kernel<<<cgrid, 256, smem_bytes>>>(x, weight, in_map, out_map, out);

    stats_kernel<<<592, 256>>>(out);
    finalize_kernel<<<1, 64>>>(gamma, beta);

    long long n4 = (long long)out_size / 4;
    norm_kernel<<<(int)((n4 + 255) / 256), 256>>>(out, n4);
}

// round 8
// speedup vs baseline: 3.8767x; 3.8767x over previous
#include <cuda_runtime.h>
#include <cuda_bf16.h>
#include <math.h>
#include <cstdint>

// Problem constants
#define N_IN   100000
#define N_OUT  200000
#define C_IN   128
#define C_OUT  64
#define KOFF   27
#define MPAIRS 100000
#define BN_EPS 1e-5f

// Tiling: warp-chunks of 32 pairs; 3125 chunks per k (exact, no tail).
#define NCHUNKS      3125
#define BLOCKS_X     22
#define WARPS_PER_B  4
#define STREAMS      (BLOCKS_X * WARPS_PER_B)   // 88 warp-streams per k

// SMEM layout (bytes):
//  B0 (w0 bf16 [128k x 64n], 144B row stride): [0, 18432)
//  B1 (w1):                                    [18432, 36864)
//  A per warp, per split: 32 rows x 272B:      [36864 + wid*17408 + split*8704)
#define B_STRIDE   144
#define B1_OFF     18432
#define A_OFF      36864
#define A_STRIDE   272
#define A_SPLIT_SZ 8704
#define A_WARP_SZ  17408
#define SMEM_TOTAL (A_OFF + WARPS_PER_B * A_WARP_SZ)   // 106496

// BN scratch (no cudaMalloc -> __device__ globals)
__device__ float g_sum[C_OUT];
__device__ float g_sq[C_OUT];
__device__ float g_scale[C_OUT];
__device__ float g_bias[C_OUT];

// ======================= helpers =======================
__device__ __forceinline__ uint32_t smem_u32(const void* p) {
    uint32_t a;
    asm("{ .reg .u64 t; cvta.to.shared.u64 t, %1; cvt.u32.u64 %0, t; }"
        : "=r"(a) : "l"(p));
    return a;
}
// pack two floats to bf16x2 (lo, hi)
__device__ __forceinline__ uint32_t cvt_bf16x2(float lo, float hi) {
    uint32_t r;
    asm("cvt.rn.bf16x2.f32 %0, %1, %2;" : "=r"(r) : "f"(hi), "f"(lo));
    return r;
}
__device__ __forceinline__ void ldmx4(uint32_t r[4], uint32_t addr) {
    asm volatile("ldmatrix.sync.aligned.m8n8.x4.shared.b16 {%0,%1,%2,%3}, [%4];"
                 : "=r"(r[0]), "=r"(r[1]), "=r"(r[2]), "=r"(r[3]) : "r"(addr));
}
__device__ __forceinline__ void ldmx4t(uint32_t r[4], uint32_t addr) {
    asm volatile("ldmatrix.sync.aligned.m8n8.x4.trans.shared.b16 {%0,%1,%2,%3}, [%4];"
                 : "=r"(r[0]), "=r"(r[1]), "=r"(r[2]), "=r"(r[3]) : "r"(addr));
}
__device__ __forceinline__ void mma_bf16(float* c, const uint32_t* a,
                                         uint32_t b0, uint32_t b1) {
    asm volatile(
        "mma.sync.aligned.m16n8k16.row.col.f32.bf16.bf16.f32 "
        "{%0,%1,%2,%3}, {%4,%5,%6,%7}, {%8,%9}, {%0,%1,%2,%3};"
        : "+f"(c[0]), "+f"(c[1]), "+f"(c[2]), "+f"(c[3])
        : "r"(a[0]), "r"(a[1]), "r"(a[2]), "r"(a[3]), "r"(b0), "r"(b1));
}

// ---------------------------------------------------------------------------
// Tensor-core conv via mma.sync bf16 3-term split.
// grid = (22, 27); block = 128 threads (4 warps); 2 CTA/SM (smem-limited).
// blockIdx.y = kernel offset k. Warp g = blockIdx.x*4+wid strides 32-pair
// chunks: gather -> bf16 split -> STS A tile -> 384 HMMA -> RED scatter.
// ---------------------------------------------------------------------------
__global__ void __launch_bounds__(128) conv_mma_kernel(
    const float* __restrict__ x,
    const float* __restrict__ weight,
    const int*   __restrict__ in_map,
    const int*   __restrict__ out_map,
    float*       __restrict__ out)
{
    extern __shared__ unsigned char smemc[];
    const int tid  = threadIdx.x;
    const int lane = tid & 31;
    const int wid  = tid >> 5;
    const int k    = blockIdx.y;

    // ---- stage weight[k] split (w0, w1) into SMEM B tiles, once per block ----
    {
        const float* wk = weight + (size_t)k * C_IN * C_OUT;
        for (int i = tid; i < C_IN * C_OUT; i += 128) {
            const int ci = i >> 6;   // GEMM K index (c_in)
            const int n  = i & 63;   // GEMM N index (c_out)
            const float wv = wk[i];
            __nv_bfloat16 h0 = __float2bfloat16(wv);
            __nv_bfloat16 h1 = __float2bfloat16(wv - __bfloat162float(h0));
            *(unsigned short*)(smemc + ci * B_STRIDE + n * 2) =
                __bfloat16_as_ushort(h0);
            *(unsigned short*)(smemc + B1_OFF + ci * B_STRIDE + n * 2) =
                __bfloat16_as_ushort(h1);
        }
    }
    __syncthreads();

    const uint32_t sbase = smem_u32(smemc);
    // per-thread invariant ldmatrix address parts
    const uint32_t aPart  = (uint32_t)((lane & 15) * A_STRIDE + (lane >> 4) * 16);
    const uint32_t aBase0 = sbase + A_OFF + wid * A_WARP_SZ;
    const uint32_t aBase1 = aBase0 + A_SPLIT_SZ;
    const uint32_t bPart  =
        (uint32_t)(((lane & 7) + ((lane >> 3) & 1) * 8) * B_STRIDE + (lane >> 4) * 16);
    const uint32_t bBase0 = sbase + bPart;
    const uint32_t bBase1 = sbase + B1_OFF + bPart;
    unsigned char* aPtr = smemc + A_OFF + wid * A_WARP_SZ;

    const int g = blockIdx.x * WARPS_PER_B + wid;

    for (int c = g; c < NCHUNKS; c += STREAMS) {
        const int pair = c * 32 + lane;          // always < MPAIRS (exact fit)
        const int gi   = k * MPAIRS + pair;
        const int my_ir = in_map[gi];
        const int my_or = out_map[gi];

        // ---- gather 32 rows, split to bf16 (x0, x1), stage to A tiles ----
        #pragma unroll 4
        for (int r = 0; r < 32; r++) {
            const int ir = __shfl_sync(0xffffffffu, my_ir, r);
            float4 v = ((const float4*)(x + (size_t)ir * C_IN))[lane];
            uint32_t u0 = cvt_bf16x2(v.x, v.y);
            uint32_t u1 = cvt_bf16x2(v.z, v.w);
            float lx = __uint_as_float(u0 << 16);
            float ly = __uint_as_float(u0 & 0xffff0000u);
            float lz = __uint_as_float(u1 << 16);
            float lw = __uint_as_float(u1 & 0xffff0000u);
            uint32_t e0 = cvt_bf16x2(v.x - lx, v.y - ly);
            uint32_t e1 = cvt_bf16x2(v.z - lz, v.w - lw);
            *(uint2*)(aPtr + r * A_STRIDE + lane * 8) = make_uint2(u0, u1);
            *(uint2*)(aPtr + A_SPLIT_SZ + r * A_STRIDE + lane * 8) = make_uint2(e0, e1);
        }
        __syncwarp();

        // ---- MMA mainloop: 8 K-steps, 3 split terms ----
        float acc[2][8][4];
        #pragma unroll
        for (int ms = 0; ms < 2; ms++)
            #pragma unroll
            for (int nt = 0; nt < 8; nt++)
                #pragma unroll
                for (int q = 0; q < 4; q++) acc[ms][nt][q] = 0.f;

        #pragma unroll
        for (int ks = 0; ks < 8; ks++) {
            uint32_t A[2][2][4];   // [ms][split][4]
            ldmx4(A[0][0], aBase0 + ks * 32 + aPart);
            ldmx4(A[1][0], aBase0 + 16 * A_STRIDE + ks * 32 + aPart);
            ldmx4(A[0][1], aBase1 + ks * 32 + aPart);
            ldmx4(A[1][1], aBase1 + 16 * A_STRIDE + ks * 32 + aPart);

            uint32_t B0[4][4], B1[4][4];   // [ng][4]; regs 0,1=k-lo/hi n-lo; 2,3=n-hi
            #pragma unroll
            for (int ng = 0; ng < 4; ng++) {
                ldmx4t(B0[ng], bBase0 + ks * 16 * B_STRIDE + ng * 32);
                ldmx4t(B1[ng], bBase1 + ks * 16 * B_STRIDE + ng * 32);
            }

            #pragma unroll
            for (int ms = 0; ms < 2; ms++) {
                #pragma unroll
                for (int nt = 0; nt < 8; nt++) {
                    const int ng = nt >> 1;
                    const int pp = (nt & 1) * 2;
                    mma_bf16(acc[ms][nt], A[ms][0], B0[ng][pp], B0[ng][pp + 1]);
                    mma_bf16(acc[ms][nt], A[ms][1], B0[ng][pp], B0[ng][pp + 1]);
                    mma_bf16(acc[ms][nt], A[ms][0], B1[ng][pp], B1[ng][pp + 1]);
                }
            }
        }
        __syncwarp();   // all ldmatrix done before next chunk's STS

        // ---- scatter-add: rows ms*16 + lane/4 (+8), cols nt*8 + (lane&3)*2 ----
        #pragma unroll
        for (int ms = 0; ms < 2; ms++) {
            const int row0 = ms * 16 + (lane >> 2);
            const int or0 = __shfl_sync(0xffffffffu, my_or, row0);
            const int or1 = __shfl_sync(0xffffffffu, my_or, row0 + 8);
            float* d0 = out + (size_t)or0 * C_OUT + (lane & 3) * 2;
            float* d1 = out + (size_t)or1 * C_OUT + (lane & 3) * 2;
            #pragma unroll
            for (int nt = 0; nt < 8; nt++) {
                asm volatile("red.global.add.v2.f32 [%0], {%1, %2};"
                             :: "l"(d0 + nt * 8),
                                "f"(acc[ms][nt][0]), "f"(acc[ms][nt][1]) : "memory");
                asm volatile("red.global.add.v2.f32 [%0], {%1, %2};"
                             :: "l"(d1 + nt * 8),
                                "f"(acc[ms][nt][2]), "f"(acc[ms][nt][3]) : "memory");
            }
        }
    }
}

// ---------------------------------------------------------------------------
// BN + ReLU chain (unchanged from the 1116us baseline)
// ---------------------------------------------------------------------------
__global__ void zero_stats_kernel() {
    if (threadIdx.x < C_OUT) { g_sum[threadIdx.x] = 0.f; g_sq[threadIdx.x] = 0.f; }
}

__global__ void stats_kernel(const float* __restrict__ out) {
    const int c    = threadIdx.x & 63;
    const int rsub = threadIdx.x >> 6;
    float s = 0.f, q = 0.f;
    for (int r = blockIdx.x * 4 + rsub; r < N_OUT; r += gridDim.x * 4) {
        float v = out[(size_t)r * C_OUT + c];
        s += v;
        q = fmaf(v, v, q);
    }
    __shared__ float ssh[256];
    __shared__ float qsh[256];
    ssh[threadIdx.x] = s;
    qsh[threadIdx.x] = q;
    __syncthreads();
    if (rsub == 0) {
        s = ssh[c] + ssh[c + 64] + ssh[c + 128] + ssh[c + 192];
        q = qsh[c] + qsh[c + 64] + qsh[c + 128] + qsh[c + 192];
        atomicAdd(&g_sum[c], s);
        atomicAdd(&g_sq[c], q);
    }
}

__global__ void finalize_kernel(const float* __restrict__ gamma,
                                const float* __restrict__ beta) {
    const int c = threadIdx.x;
    if (c < C_OUT) {
        const float invn = 1.0f / (float)N_OUT;
        float mean = g_sum[c] * invn;
        float var  = g_sq[c] * invn - mean * mean;
        float sc   = gamma[c] * rsqrtf(var + BN_EPS);
        g_scale[c] = sc;
        g_bias[c]  = beta[c] - mean * sc;
    }
}

__global__ void norm_kernel(float* __restrict__ out, long long n4) {
    long long i = (long long)blockIdx.x * blockDim.x + threadIdx.x;
    if (i < n4) {
        float4 v = ((float4*)out)[i];
        int c0 = (int)((i * 4) & 63);
        v.x = fmaxf(fmaf(v.x, g_scale[c0 + 0], g_bias[c0 + 0]), 0.f);
        v.y = fmaxf(fmaf(v.y, g_scale[c0 + 1], g_bias[c0 + 1]), 0.f);
        v.z = fmaxf(fmaf(v.z, g_scale[c0 + 2], g_bias[c0 + 2]), 0.f);
        v.w = fmaxf(fmaf(v.w, g_scale[c0 + 3], g_bias[c0 + 3]), 0.f);
        ((float4*)out)[i] = v;
    }
}

// ---------------------------------------------------------------------------
// kernel_launch — graph-capturable, default stream
// Inputs (metadata order): x, weight, gamma, beta, in_map, out_map
// ---------------------------------------------------------------------------
extern "C" void kernel_launch(void* const* d_in, const int* in_sizes, int n_in,
                              void* d_out, int out_size)
{
    const float* x       = (const float*)d_in[0];
    const float* weight  = (const float*)d_in[1];
    const float* gamma   = (const float*)d_in[2];
    const float* beta    = (const float*)d_in[3];
    const int*   in_map  = (const int*)d_in[4];
    const int*   out_map = (const int*)d_in[5];
    float*       out     = (float*)d_out;

    cudaMemsetAsync(out, 0, (size_t)out_size * sizeof(float));
    zero_stats_kernel<<<1, 64>>>();

    cudaFuncSetAttribute(conv_mma_kernel,
                         cudaFuncAttributeMaxDynamicSharedMemorySize, SMEM_TOTAL);
    dim3 cgrid(BLOCKS_X, KOFF);
    conv_mma_kernel<<<cgrid, 128, SMEM_TOTAL>>>(x, weight, in_map, out_map, out);

    stats_kernel<<<592, 256>>>(out);
    finalize_kernel<<<1, 64>>>(gamma, beta);

    long long n4 = (long long)out_size / 4;
    norm_kernel<<<(int)((n4 + 255) / 256), 256>>>(out, n4);
}

// round 9
// speedup vs baseline: 5.4354x; 1.4021x over previous
#include <cuda_runtime.h>
#include <cuda_bf16.h>
#include <math.h>
#include <cstdint>

// Problem constants
#define N_IN   100000
#define N_OUT  200000
#define C_IN   128
#define C_OUT  64
#define KOFF   27
#define MPAIRS 100000
#define BN_EPS 1e-5f

// Tiling: warp-chunks of 32 pairs; 3125 chunks per k (exact, no tail).
#define NCHUNKS      3125
#define BLOCKS_X     16
#define WARPS_PER_B  4
#define STREAMS      (BLOCKS_X * WARPS_PER_B)   // 64 warp-streams per k

// SMEM: B0 (w0 bf16 [128k x 64n], 144B row stride) + B1
#define B_STRIDE   144
#define B1_OFF     18432
#define SMEM_TOTAL 36864

// Pre-split x in fragment-permuted bf16 layout:
//   element e = ks*16 + q*4 + h*2 + l  <->  column c = ks*16 + h*8 + q*2 + l
__device__ __align__(16) uint16_t g_x0[N_IN * C_IN];
__device__ __align__(16) uint16_t g_x1[N_IN * C_IN];

// BN scratch
__device__ float g_sum[C_OUT];
__device__ float g_sq[C_OUT];

// ======================= helpers =======================
__device__ __forceinline__ uint32_t smem_u32(const void* p) {
    uint32_t a;
    asm("{ .reg .u64 t; cvta.to.shared.u64 t, %1; cvt.u32.u64 %0, t; }"
        : "=r"(a) : "l"(p));
    return a;
}
__device__ __forceinline__ uint32_t cvt_bf16x2(float lo, float hi) {
    uint32_t r;
    asm("cvt.rn.bf16x2.f32 %0, %1, %2;" : "=r"(r) : "f"(hi), "f"(lo));
    return r;
}
__device__ __forceinline__ void ldmx4t(uint32_t r[4], uint32_t addr) {
    asm volatile("ldmatrix.sync.aligned.m8n8.x4.trans.shared.b16 {%0,%1,%2,%3}, [%4];"
                 : "=r"(r[0]), "=r"(r[1]), "=r"(r[2]), "=r"(r[3]) : "r"(addr));
}
__device__ __forceinline__ void mma_bf16(float* c, const uint32_t* a,
                                         uint32_t b0, uint32_t b1) {
    asm volatile(
        "mma.sync.aligned.m16n8k16.row.col.f32.bf16.bf16.f32 "
        "{%0,%1,%2,%3}, {%4,%5,%6,%7}, {%8,%9}, {%0,%1,%2,%3};"
        : "+f"(c[0]), "+f"(c[1]), "+f"(c[2]), "+f"(c[3])
        : "r"(a[0]), "r"(a[1]), "r"(a[2]), "r"(a[3]), "r"(b0), "r"(b1));
}

// ---------------------------------------------------------------------------
// Prep: split x to bf16 (x0 = rn(x), x1 = rn(x - x0)) in permuted layout.
// Thread = (row, ks, q): reads cols {16ks+2q, +1, +8, +9}, writes 8B per array.
// Block 0 also zeroes BN accumulators.
// ---------------------------------------------------------------------------
__global__ void prep_kernel(const float* __restrict__ x) {
    if (blockIdx.x == 0 && threadIdx.x < C_OUT) {
        g_sum[threadIdx.x] = 0.f;
        g_sq[threadIdx.x]  = 0.f;
    }
    const int t = blockIdx.x * blockDim.x + threadIdx.x;
    if (t >= N_IN * 32) return;
    const int row = t >> 5;
    const int ks  = (t & 31) >> 2;
    const int q   = t & 3;

    const float* xr = x + (size_t)row * C_IN + ks * 16 + 2 * q;
    float2 va = *(const float2*)xr;        // cols c, c+1
    float2 vb = *(const float2*)(xr + 8);  // cols c+8, c+9

    uint32_t h01 = cvt_bf16x2(va.x, va.y);
    uint32_t h23 = cvt_bf16x2(vb.x, vb.y);
    float l0 = __uint_as_float(h01 << 16);
    float l1 = __uint_as_float(h01 & 0xffff0000u);
    float l2 = __uint_as_float(h23 << 16);
    float l3 = __uint_as_float(h23 & 0xffff0000u);
    uint32_t e01 = cvt_bf16x2(va.x - l0, va.y - l1);
    uint32_t e23 = cvt_bf16x2(vb.x - l2, vb.y - l3);

    const size_t e = (size_t)row * C_IN + ks * 16 + q * 4;
    *(uint2*)(g_x0 + e) = make_uint2(h01, h23);
    *(uint2*)(g_x1 + e) = make_uint2(e01, e23);
}

// ---------------------------------------------------------------------------
// Conv: mma.sync bf16 3-term split (x0w0 + x1w0 + x0w1), A fragments loaded
// directly from pre-split global (one LDG.64 per row-half), B from SMEM.
// grid = (16, 27); block = 128 (4 warps). No block syncs in the hot loop.
// ---------------------------------------------------------------------------
__global__ void __launch_bounds__(128, 3) conv_mma_kernel(
    const float* __restrict__ weight,
    const int*   __restrict__ in_map,
    const int*   __restrict__ out_map,
    float*       __restrict__ out)
{
    extern __shared__ unsigned char smemc[];
    const int tid  = threadIdx.x;
    const int lane = tid & 31;
    const int wid  = tid >> 5;
    const int k    = blockIdx.y;

    // ---- stage weight[k] split (w0, w1) into SMEM B tiles, once per block ----
    {
        const float* wk = weight + (size_t)k * C_IN * C_OUT;
        for (int i = tid; i < C_IN * C_OUT; i += 128) {
            const int ci = i >> 6;
            const int n  = i & 63;
            const float wv = wk[i];
            __nv_bfloat16 h0 = __float2bfloat16(wv);
            __nv_bfloat16 h1 = __float2bfloat16(wv - __bfloat162float(h0));
            *(unsigned short*)(smemc + ci * B_STRIDE + n * 2) =
                __bfloat16_as_ushort(h0);
            *(unsigned short*)(smemc + B1_OFF + ci * B_STRIDE + n * 2) =
                __bfloat16_as_ushort(h1);
        }
    }
    __syncthreads();

    const uint32_t sbase = smem_u32(smemc);
    const uint32_t bPart =
        (uint32_t)(((lane & 7) + ((lane >> 3) & 1) * 8) * B_STRIDE + (lane >> 4) * 16);
    const uint32_t bBase0 = sbase + bPart;
    const uint32_t bBase1 = sbase + B1_OFF + bPart;

    const int q = lane & 3;
    const int g = blockIdx.x * WARPS_PER_B + wid;

    for (int c = g; c < NCHUNKS; c += STREAMS) {
        const int pair  = c * 32 + lane;
        const int gi    = k * MPAIRS + pair;
        const int my_ir = in_map[gi];
        const int my_or = out_map[gi];

        // Fragment row pointers: [ms][rowhalf] (element offsets incl. q*4)
        const uint16_t* pa[2][2];
        #pragma unroll
        for (int ms = 0; ms < 2; ms++) {
            const int rlo = __shfl_sync(0xffffffffu, my_ir, ms * 16 + (lane >> 2));
            const int rhi = __shfl_sync(0xffffffffu, my_ir, ms * 16 + 8 + (lane >> 2));
            pa[ms][0] = g_x0 + (size_t)rlo * C_IN + q * 4;
            pa[ms][1] = g_x0 + (size_t)rhi * C_IN + q * 4;
        }
        const size_t split_off = (size_t)(g_x1 - g_x0);

        float acc[2][8][4];
        #pragma unroll
        for (int ms = 0; ms < 2; ms++)
            #pragma unroll
            for (int nt = 0; nt < 8; nt++)
                #pragma unroll
                for (int u = 0; u < 4; u++) acc[ms][nt][u] = 0.f;

        #pragma unroll
        for (int ks = 0; ks < 8; ks++) {
            // A fragments straight from global: [ms][split][4]
            uint32_t A[2][2][4];
            #pragma unroll
            for (int ms = 0; ms < 2; ms++) {
                uint2 lo0 = *(const uint2*)(pa[ms][0] + ks * 16);
                uint2 hi0 = *(const uint2*)(pa[ms][1] + ks * 16);
                uint2 lo1 = *(const uint2*)(pa[ms][0] + split_off + ks * 16);
                uint2 hi1 = *(const uint2*)(pa[ms][1] + split_off + ks * 16);
                A[ms][0][0] = lo0.x; A[ms][0][1] = hi0.x;
                A[ms][0][2] = lo0.y; A[ms][0][3] = hi0.y;
                A[ms][1][0] = lo1.x; A[ms][1][1] = hi1.x;
                A[ms][1][2] = lo1.y; A[ms][1][3] = hi1.y;
            }

            uint32_t B0[4][4], B1[4][4];
            #pragma unroll
            for (int ng = 0; ng < 4; ng++) {
                ldmx4t(B0[ng], bBase0 + ks * 16 * B_STRIDE + ng * 32);
                ldmx4t(B1[ng], bBase1 + ks * 16 * B_STRIDE + ng * 32);
            }

            #pragma unroll
            for (int ms = 0; ms < 2; ms++) {
                #pragma unroll
                for (int nt = 0; nt < 8; nt++) {
                    const int ng = nt >> 1;
                    const int pp = (nt & 1) * 2;
                    mma_bf16(acc[ms][nt], A[ms][0], B0[ng][pp], B0[ng][pp + 1]);
                    mma_bf16(acc[ms][nt], A[ms][1], B0[ng][pp], B0[ng][pp + 1]);
                    mma_bf16(acc[ms][nt], A[ms][0], B1[ng][pp], B1[ng][pp + 1]);
                }
            }
        }

        // ---- scatter-add ----
        #pragma unroll
        for (int ms = 0; ms < 2; ms++) {
            const int row0 = ms * 16 + (lane >> 2);
            const int or0 = __shfl_sync(0xffffffffu, my_or, row0);
            const int or1 = __shfl_sync(0xffffffffu, my_or, row0 + 8);
            float* d0 = out + (size_t)or0 * C_OUT + q * 2;
            float* d1 = out + (size_t)or1 * C_OUT + q * 2;
            #pragma unroll
            for (int nt = 0; nt < 8; nt++) {
                asm volatile("red.global.add.v2.f32 [%0], {%1, %2};"
                             :: "l"(d0 + nt * 8),
                                "f"(acc[ms][nt][0]), "f"(acc[ms][nt][1]) : "memory");
                asm volatile("red.global.add.v2.f32 [%0], {%1, %2};"
                             :: "l"(d1 + nt * 8),
                                "f"(acc[ms][nt][2]), "f"(acc[ms][nt][3]) : "memory");
            }
        }
    }
}

// ---------------------------------------------------------------------------
// Per-channel sum / sumsq over [N_OUT, 64]
// ---------------------------------------------------------------------------
__global__ void stats_kernel(const float* __restrict__ out) {
    const int c    = threadIdx.x & 63;
    const int rsub = threadIdx.x >> 6;
    float s = 0.f, q = 0.f;
    for (int r = blockIdx.x * 4 + rsub; r < N_OUT; r += gridDim.x * 4) {
        float v = out[(size_t)r * C_OUT + c];
        s += v;
        q = fmaf(v, v, q);
    }
    __shared__ float ssh[256];
    __shared__ float qsh[256];
    ssh[threadIdx.x] = s;
    qsh[threadIdx.x] = q;
    __syncthreads();
    if (rsub == 0) {
        s = ssh[c] + ssh[c + 64] + ssh[c + 128] + ssh[c + 192];
        q = qsh[c] + qsh[c + 64] + qsh[c + 128] + qsh[c + 192];
        atomicAdd(&g_sum[c], s);
        atomicAdd(&g_sq[c], q);
    }
}

// ---------------------------------------------------------------------------
// Normalize + ReLU with inline BN finalize (per-block, cheap)
// ---------------------------------------------------------------------------
__global__ void norm_kernel(float* __restrict__ out,
                            const float* __restrict__ gamma,
                            const float* __restrict__ beta,
                            long long n4) {
    __shared__ float s_scale[C_OUT];
    __shared__ float s_bias[C_OUT];
    if (threadIdx.x < C_OUT) {
        const int c = threadIdx.x;
        const float invn = 1.0f / (float)N_OUT;
        float mean = g_sum[c] * invn;
        float var  = g_sq[c] * invn - mean * mean;
        float sc   = gamma[c] * rsqrtf(var + BN_EPS);
        s_scale[c] = sc;
        s_bias[c]  = beta[c] - mean * sc;
    }
    __syncthreads();
    long long i = (long long)blockIdx.x * blockDim.x + threadIdx.x;
    if (i < n4) {
        float4 v = ((float4*)out)[i];
        int c0 = (int)((i * 4) & 63);
        v.x = fmaxf(fmaf(v.x, s_scale[c0 + 0], s_bias[c0 + 0]), 0.f);
        v.y = fmaxf(fmaf(v.y, s_scale[c0 + 1], s_bias[c0 + 1]), 0.f);
        v.z = fmaxf(fmaf(v.z, s_scale[c0 + 2], s_bias[c0 + 2]), 0.f);
        v.w = fmaxf(fmaf(v.w, s_scale[c0 + 3], s_bias[c0 + 3]), 0.f);
        ((float4*)out)[i] = v;
    }
}

// ---------------------------------------------------------------------------
// kernel_launch — graph-capturable, default stream
// Inputs (metadata order): x, weight, gamma, beta, in_map, out_map
// ---------------------------------------------------------------------------
extern "C" void kernel_launch(void* const* d_in, const int* in_sizes, int n_in,
                              void* d_out, int out_size)
{
    const float* x       = (const float*)d_in[0];
    const float* weight  = (const float*)d_in[1];
    const float* gamma   = (const float*)d_in[2];
    const float* beta    = (const float*)d_in[3];
    const int*   in_map  = (const int*)d_in[4];
    const int*   out_map = (const int*)d_in[5];
    float*       out     = (float*)d_out;

    cudaMemsetAsync(out, 0, (size_t)out_size * sizeof(float));

    prep_kernel<<<(N_IN * 32 + 255) / 256, 256>>>(x);

    cudaFuncSetAttribute(conv_mma_kernel,
                         cudaFuncAttributeMaxDynamicSharedMemorySize, SMEM_TOTAL);
    dim3 cgrid(BLOCKS_X, KOFF);
    conv_mma_kernel<<<cgrid, 128, SMEM_TOTAL>>>(weight, in_map, out_map, out);

    stats_kernel<<<592, 256>>>(out);

    long long n4 = (long long)out_size / 4;
    norm_kernel<<<(int)((n4 + 255) / 256), 256>>>(out, gamma, beta, n4);
}

// round 12
// speedup vs baseline: 5.7925x; 1.0657x over previous
#include <cuda_runtime.h>
#include <cuda_bf16.h>
#include <math.h>
#include <cstdint>

// Problem constants
#define N_IN   100000
#define N_OUT  200000
#define C_IN   128
#define C_OUT  64
#define KOFF   27
#define MPAIRS 100000
#define BN_EPS 1e-5f

// Tiling: warp-chunks of 32 pairs; 3125 chunks per k (exact, no tail).
#define NCHUNKS      3125
#define BLOCKS_X     16
#define WARPS_PER_B  4
#define STREAMS      (BLOCKS_X * WARPS_PER_B)   // 64 warp-streams per k

// SMEM: B0 (w0 bf16 [128k x 64n], 144B row stride) + B1
#define B_STRIDE   144
#define B1_OFF     18432
#define SMEM_TOTAL 36864

// Interleaved pre-split x, bf16, fragment-permuted:
// per row: 32 granules of 8 uint16; granule gidx = ks*4 + q holds
//   [x0 elems e..e+3 | x1 elems e..e+3], e = ks*16 + q*4
// element e = ks*16 + q*4 + h*2 + l  <->  column c = ks*16 + h*8 + q*2 + l
__device__ __align__(16) uint16_t g_xs[(size_t)N_IN * C_IN * 2];

// BN scratch
__device__ float g_sum[C_OUT];
__device__ float g_sq[C_OUT];

// ======================= helpers =======================
__device__ __forceinline__ uint32_t smem_u32(const void* p) {
    uint32_t a;
    asm("{ .reg .u64 t; cvta.to.shared.u64 t, %1; cvt.u32.u64 %0, t; }"
        : "=r"(a) : "l"(p));
    return a;
}
__device__ __forceinline__ uint32_t cvt_bf16x2(float lo, float hi) {
    uint32_t r;
    asm("cvt.rn.bf16x2.f32 %0, %1, %2;" : "=r"(r) : "f"(hi), "f"(lo));
    return r;
}
__device__ __forceinline__ void ldmx4t(uint32_t r[4], uint32_t addr) {
    asm volatile("ldmatrix.sync.aligned.m8n8.x4.trans.shared.b16 {%0,%1,%2,%3}, [%4];"
                 : "=r"(r[0]), "=r"(r[1]), "=r"(r[2]), "=r"(r[3]) : "r"(addr));
}
__device__ __forceinline__ void mma_bf16(float* c, const uint32_t* a,
                                         uint32_t b0, uint32_t b1) {
    asm volatile(
        "mma.sync.aligned.m16n8k16.row.col.f32.bf16.bf16.f32 "
        "{%0,%1,%2,%3}, {%4,%5,%6,%7}, {%8,%9}, {%0,%1,%2,%3};"
        : "+f"(c[0]), "+f"(c[1]), "+f"(c[2]), "+f"(c[3])
        : "r"(a[0]), "r"(a[1]), "r"(a[2]), "r"(a[3]), "r"(b0), "r"(b1));
}

// ---------------------------------------------------------------------------
// Prep: split x to bf16 (x0 = rn(x), x1 = rn(x - x0)), interleaved layout.
// Thread = (row, ks, q). Block 0 also zeroes BN accumulators.
// ---------------------------------------------------------------------------
__global__ void prep_kernel(const float* __restrict__ x) {
    if (blockIdx.x == 0 && threadIdx.x < C_OUT) {
        g_sum[threadIdx.x] = 0.f;
        g_sq[threadIdx.x]  = 0.f;
    }
    const int t = blockIdx.x * blockDim.x + threadIdx.x;
    if (t >= N_IN * 32) return;
    const int row = t >> 5;
    const int ks  = (t & 31) >> 2;
    const int q   = t & 3;

    const float* xr = x + (size_t)row * C_IN + ks * 16 + 2 * q;
    float2 va = *(const float2*)xr;        // cols c, c+1   (h=0)
    float2 vb = *(const float2*)(xr + 8);  // cols c+8, c+9 (h=1)

    uint32_t h01 = cvt_bf16x2(va.x, va.y);
    uint32_t h23 = cvt_bf16x2(vb.x, vb.y);
    float l0 = __uint_as_float(h01 << 16);
    float l1 = __uint_as_float(h01 & 0xffff0000u);
    float l2 = __uint_as_float(h23 << 16);
    float l3 = __uint_as_float(h23 & 0xffff0000u);
    uint32_t e01 = cvt_bf16x2(va.x - l0, va.y - l1);
    uint32_t e23 = cvt_bf16x2(vb.x - l2, vb.y - l3);

    // granule: [x0(4), x1(4)] at row*256 + (ks*4+q)*8 uint16s
    uint4 gr = make_uint4(h01, h23, e01, e23);
    *(uint4*)(g_xs + (size_t)row * 256 + (size_t)(ks * 4 + q) * 8) = gr;
}

// ---------------------------------------------------------------------------
// Conv: mma.sync bf16 3-term split (x0w0 + x1w0 + x0w1).
// A fragments: one LDG.128 per (ms, rowhalf, ks) from interleaved g_xs.
// B fragments: ldmatrix from SMEM. Map loads software-pipelined one chunk
// ahead so their L2 latency hides behind the 192-HMMA mainloop.
// grid = (16, 27); block = 128 (4 warps); 3 CTA/SM.
// ---------------------------------------------------------------------------
__global__ void __launch_bounds__(128, 3) conv_mma_kernel(
    const float* __restrict__ weight,
    const int*   __restrict__ in_map,
    const int*   __restrict__ out_map,
    float*       __restrict__ out)
{
    extern __shared__ unsigned char smemc[];
    const int tid  = threadIdx.x;
    const int lane = tid & 31;
    const int wid  = tid >> 5;
    const int k    = blockIdx.y;

    // ---- stage weight[k] split (w0, w1) into SMEM B tiles, once per block ----
    {
        const float* wk = weight + (size_t)k * C_IN * C_OUT;
        for (int i = tid; i < C_IN * C_OUT; i += 128) {
            const int ci = i >> 6;
            const int n  = i & 63;
            const float wv = wk[i];
            __nv_bfloat16 h0 = __float2bfloat16(wv);
            __nv_bfloat16 h1 = __float2bfloat16(wv - __bfloat162float(h0));
            *(unsigned short*)(smemc + ci * B_STRIDE + n * 2) =
                __bfloat16_as_ushort(h0);
            *(unsigned short*)(smemc + B1_OFF + ci * B_STRIDE + n * 2) =
                __bfloat16_as_ushort(h1);
        }
    }
    __syncthreads();

    const uint32_t sbase = smem_u32(smemc);
    const uint32_t bPart =
        (uint32_t)(((lane & 7) + ((lane >> 3) & 1) * 8) * B_STRIDE + (lane >> 4) * 16);
    const uint32_t bBase0 = sbase + bPart;
    const uint32_t bBase1 = sbase + B1_OFF + bPart;

    const int q = lane & 3;
    const int g = blockIdx.x * WARPS_PER_B + wid;
    const uint16_t* xq = g_xs + q * 8;   // per-thread q offset folded in

    // prologue: load first chunk's maps
    int cur_ir = 0, cur_or = 0;
    if (g < NCHUNKS) {
        const int gi0 = k * MPAIRS + g * 32 + lane;
        cur_ir = in_map[gi0];
        cur_or = out_map[gi0];
    }

    for (int c = g; c < NCHUNKS; c += STREAMS) {
        // prefetch next chunk's maps (hidden behind this chunk's MMA work)
        int nxt_ir = 0, nxt_or = 0;
        const int nc = c + STREAMS;
        if (nc < NCHUNKS) {
            const int gin = k * MPAIRS + nc * 32 + lane;
            nxt_ir = in_map[gin];
            nxt_or = out_map[gin];
        }

        // Fragment row pointers: [ms][rowhalf]
        const uint16_t* pa[2][2];
        #pragma unroll
        for (int ms = 0; ms < 2; ms++) {
            const int rlo = __shfl_sync(0xffffffffu, cur_ir, ms * 16 + (lane >> 2));
            const int rhi = __shfl_sync(0xffffffffu, cur_ir, ms * 16 + 8 + (lane >> 2));
            pa[ms][0] = xq + (size_t)rlo * 256;
            pa[ms][1] = xq + (size_t)rhi * 256;
        }

        float acc[2][8][4];
        #pragma unroll
        for (int ms = 0; ms < 2; ms++)
            #pragma unroll
            for (int nt = 0; nt < 8; nt++)
                #pragma unroll
                for (int u = 0; u < 4; u++) acc[ms][nt][u] = 0.f;

        #pragma unroll
        for (int ks = 0; ks < 8; ks++) {
            // A fragments: one LDG.128 per (ms, half) carrying both splits
            uint32_t A[2][2][4];   // [ms][split][4]
            #pragma unroll
            for (int ms = 0; ms < 2; ms++) {
                uint4 lo = *(const uint4*)(pa[ms][0] + ks * 32);
                uint4 hi = *(const uint4*)(pa[ms][1] + ks * 32);
                A[ms][0][0] = lo.x; A[ms][0][1] = hi.x;
                A[ms][0][2] = lo.y; A[ms][0][3] = hi.y;
                A[ms][1][0] = lo.z; A[ms][1][1] = hi.z;
                A[ms][1][2] = lo.w; A[ms][1][3] = hi.w;
            }

            uint32_t B0[4][4], B1[4][4];
            #pragma unroll
            for (int ng = 0; ng < 4; ng++) {
                ldmx4t(B0[ng], bBase0 + ks * 16 * B_STRIDE + ng * 32);
                ldmx4t(B1[ng], bBase1 + ks * 16 * B_STRIDE + ng * 32);
            }

            #pragma unroll
            for (int ms = 0; ms < 2; ms++) {
                #pragma unroll
                for (int nt = 0; nt < 8; nt++) {
                    const int ng = nt >> 1;
                    const int pp = (nt & 1) * 2;
                    mma_bf16(acc[ms][nt], A[ms][0], B0[ng][pp], B0[ng][pp + 1]);
                    mma_bf16(acc[ms][nt], A[ms][1], B0[ng][pp], B0[ng][pp + 1]);
                    mma_bf16(acc[ms][nt], A[ms][0], B1[ng][pp], B1[ng][pp + 1]);
                }
            }
        }

        // ---- scatter-add ----
        #pragma unroll
        for (int ms = 0; ms < 2; ms++) {
            const int row0 = ms * 16 + (lane >> 2);
            const int or0 = __shfl_sync(0xffffffffu, cur_or, row0);
            const int or1 = __shfl_sync(0xffffffffu, cur_or, row0 + 8);
            float* d0 = out + (size_t)or0 * C_OUT + q * 2;
            float* d1 = out + (size_t)or1 * C_OUT + q * 2;
            #pragma unroll
            for (int nt = 0; nt < 8; nt++) {
                asm volatile("red.global.add.v2.f32 [%0], {%1, %2};"
                             :: "l"(d0 + nt * 8),
                                "f"(acc[ms][nt][0]), "f"(acc[ms][nt][1]) : "memory");
                asm volatile("red.global.add.v2.f32 [%0], {%1, %2};"
                             :: "l"(d1 + nt * 8),
                                "f"(acc[ms][nt][2]), "f"(acc[ms][nt][3]) : "memory");
            }
        }

        cur_ir = nxt_ir;
        cur_or = nxt_or;
    }
}

// ---------------------------------------------------------------------------
// Per-channel sum / sumsq over [N_OUT, 64]
// ---------------------------------------------------------------------------
__global__ void stats_kernel(const float* __restrict__ out) {
    const int c    = threadIdx.x & 63;
    const int rsub = threadIdx.x >> 6;
    float s = 0.f, q = 0.f;
    for (int r = blockIdx.x * 4 + rsub; r < N_OUT; r += gridDim.x * 4) {
        float v = out[(size_t)r * C_OUT + c];
        s += v;
        q = fmaf(v, v, q);
    }
    __shared__ float ssh[256];
    __shared__ float qsh[256];
    ssh[threadIdx.x] = s;
    qsh[threadIdx.x] = q;
    __syncthreads();
    if (rsub == 0) {
        s = ssh[c] + ssh[c + 64] + ssh[c + 128] + ssh[c + 192];
        q = qsh[c] + qsh[c + 64] + qsh[c + 128] + qsh[c + 192];
        atomicAdd(&g_sum[c], s);
        atomicAdd(&g_sq[c], q);
    }
}

// ---------------------------------------------------------------------------
// Normalize + ReLU with inline BN finalize (per-block, cheap)
// ---------------------------------------------------------------------------
__global__ void norm_kernel(float* __restrict__ out,
                            const float* __restrict__ gamma,
                            const float* __restrict__ beta,
                            long long n4) {
    __shared__ float s_scale[C_OUT];
    __shared__ float s_bias[C_OUT];
    if (threadIdx.x < C_OUT) {
        const int c = threadIdx.x;
        const float invn = 1.0f / (float)N_OUT;
        float mean = g_sum[c] * invn;
        float var  = g_sq[c] * invn - mean * mean;
        float sc   = gamma[c] * rsqrtf(var + BN_EPS);
        s_scale[c] = sc;
        s_bias[c]  = beta[c] - mean * sc;
    }
    __syncthreads();
    long long i = (long long)blockIdx.x * blockDim.x + threadIdx.x;
    if (i < n4) {
        float4 v = ((float4*)out)[i];
        int c0 = (int)((i * 4) & 63);
        v.x = fmaxf(fmaf(v.x, s_scale[c0 + 0], s_bias[c0 + 0]), 0.f);
        v.y = fmaxf(fmaf(v.y, s_scale[c0 + 1], s_bias[c0 + 1]), 0.f);
        v.z = fmaxf(fmaf(v.z, s_scale[c0 + 2], s_bias[c0 + 2]), 0.f);
        v.w = fmaxf(fmaf(v.w, s_scale[c0 + 3], s_bias[c0 + 3]), 0.f);
        ((float4*)out)[i] = v;
    }
}

// ---------------------------------------------------------------------------
// kernel_launch — graph-capturable, default stream
// Inputs (metadata order): x, weight, gamma, beta, in_map, out_map
// ---------------------------------------------------------------------------
extern "C" void kernel_launch(void* const* d_in, const int* in_sizes, int n_in,
                              void* d_out, int out_size)
{
    const float* x       = (const float*)d_in[0];
    const float* weight  = (const float*)d_in[1];
    const float* gamma   = (const float*)d_in[2];
    const float* beta    = (const float*)d_in[3];
    const int*   in_map  = (const int*)d_in[4];
    const int*   out_map = (const int*)d_in[5];
    float*       out     = (float*)d_out;

    cudaMemsetAsync(out, 0, (size_t)out_size * sizeof(float));

    prep_kernel<<<(N_IN * 32 + 255) / 256, 256>>>(x);

    cudaFuncSetAttribute(conv_mma_kernel,
                         cudaFuncAttributeMaxDynamicSharedMemorySize, SMEM_TOTAL);
    dim3 cgrid(BLOCKS_X, KOFF);
    conv_mma_kernel<<<cgrid, 128, SMEM_TOTAL>>>(weight, in_map, out_map, out);

    stats_kernel<<<592, 256>>>(out);

    long long n4 = (long long)out_size / 4;
    norm_kernel<<<(int)((n4 + 255) / 256), 256>>>(out, gamma, beta, n4);
}

// round 13
// speedup vs baseline: 7.8088x; 1.3481x over previous
#include <cuda_runtime.h>
#include <cuda_fp16.h>
#include <math.h>
#include <cstdint>

// Problem constants
#define N_IN   100000
#define N_OUT  200000
#define C_IN   128
#define C_OUT  64
#define KOFF   27
#define MPAIRS 100000
#define BN_EPS 1e-5f

// Tiling: warp-chunks of 32 pairs; 3125 chunks per k (exact, no tail).
#define NCHUNKS      3125
#define BLOCKS_X     16
#define WARPS_PER_B  4
#define STREAMS      (BLOCKS_X * WARPS_PER_B)   // 64 warp-streams per k

// SMEM: B (w fp16 [128k x 64n], 144B row stride)
#define B_STRIDE   144
#define SMEM_TOTAL 18432

// Pre-converted x, fp16, fragment-permuted, per-lane-contiguous:
// per row 128 fp16 (256B); element order: [q][ks][4] with the 4-group =
// cols {16ks+2q, 16ks+2q+1, 16ks+2q+8, 16ks+2q+9}. A lane's full K-span of
// fragments = 64 contiguous bytes at row*256 + q*64.
__device__ __align__(16) uint16_t g_xh[(size_t)N_IN * C_IN];

// BN scratch
__device__ float g_sum[C_OUT];
__device__ float g_sq[C_OUT];

// ======================= helpers =======================
__device__ __forceinline__ uint32_t smem_u32(const void* p) {
    uint32_t a;
    asm("{ .reg .u64 t; cvta.to.shared.u64 t, %1; cvt.u32.u64 %0, t; }"
        : "=r"(a) : "l"(p));
    return a;
}
__device__ __forceinline__ uint32_t cvt_f16x2(float lo, float hi) {
    uint32_t r;
    asm("cvt.rn.f16x2.f32 %0, %1, %2;" : "=r"(r) : "f"(hi), "f"(lo));
    return r;
}
__device__ __forceinline__ void ldmx4t(uint32_t r[4], uint32_t addr) {
    asm volatile("ldmatrix.sync.aligned.m8n8.x4.trans.shared.b16 {%0,%1,%2,%3}, [%4];"
                 : "=r"(r[0]), "=r"(r[1]), "=r"(r[2]), "=r"(r[3]) : "r"(addr));
}
__device__ __forceinline__ void mma_fp16(float* c, uint32_t a0, uint32_t a1,
                                         uint32_t a2, uint32_t a3,
                                         uint32_t b0, uint32_t b1) {
    asm volatile(
        "mma.sync.aligned.m16n8k16.row.col.f32.f16.f16.f32 "
        "{%0,%1,%2,%3}, {%4,%5,%6,%7}, {%8,%9}, {%0,%1,%2,%3};"
        : "+f"(c[0]), "+f"(c[1]), "+f"(c[2]), "+f"(c[3])
        : "r"(a0), "r"(a1), "r"(a2), "r"(a3), "r"(b0), "r"(b1));
}

// ---------------------------------------------------------------------------
// Prep: convert x to fp16 in per-lane-contiguous permuted layout.
// Thread = (row, ks, q): reads cols {16ks+2q, +1, +8, +9}, writes 8B.
// Block 0 also zeroes BN accumulators.
// ---------------------------------------------------------------------------
__global__ void prep_kernel(const float* __restrict__ x) {
    if (blockIdx.x == 0 && threadIdx.x < C_OUT) {
        g_sum[threadIdx.x] = 0.f;
        g_sq[threadIdx.x]  = 0.f;
    }
    const int t = blockIdx.x * blockDim.x + threadIdx.x;
    if (t >= N_IN * 32) return;
    const int row = t >> 5;
    const int ks  = (t & 31) >> 2;
    const int q   = t & 3;

    const float* xr = x + (size_t)row * C_IN + ks * 16 + 2 * q;
    float2 va = *(const float2*)xr;        // cols c, c+1
    float2 vb = *(const float2*)(xr + 8);  // cols c+8, c+9

    uint2 gr = make_uint2(cvt_f16x2(va.x, va.y), cvt_f16x2(vb.x, vb.y));
    // layout: row*128 + q*32 + ks*4 elements
    *(uint2*)(g_xh + (size_t)row * 128 + q * 32 + ks * 4) = gr;
}

// ---------------------------------------------------------------------------
// Conv: single-term fp16 mma.sync gather-GEMM-scatter.
// A fragments: 4x LDG.128 per (ms, rowhalf) cover all 8 K-steps (lane data
// is 64B contiguous). B: ldmatrix from SMEM. Maps software-pipelined.
// grid = (16, 27); block = 128 (4 warps); 4 CTA/SM.
// ---------------------------------------------------------------------------
__global__ void __launch_bounds__(128, 4) conv_mma_kernel(
    const float* __restrict__ weight,
    const int*   __restrict__ in_map,
    const int*   __restrict__ out_map,
    float*       __restrict__ out)
{
    extern __shared__ unsigned char smemc[];
    const int tid  = threadIdx.x;
    const int lane = tid & 31;
    const int wid  = tid >> 5;
    const int k    = blockIdx.y;

    // ---- stage weight[k] as fp16 into SMEM B tile, once per block ----
    {
        const float* wk = weight + (size_t)k * C_IN * C_OUT;
        for (int i = tid; i < C_IN * C_OUT; i += 128) {
            const int ci = i >> 6;
            const int n  = i & 63;
            *(unsigned short*)(smemc + ci * B_STRIDE + n * 2) =
                __half_as_ushort(__float2half_rn(wk[i]));
        }
    }
    __syncthreads();

    const uint32_t sbase = smem_u32(smemc);
    const uint32_t bPart =
        (uint32_t)(((lane & 7) + ((lane >> 3) & 1) * 8) * B_STRIDE + (lane >> 4) * 16);
    const uint32_t bBase = sbase + bPart;

    const int q = lane & 3;
    const int g = blockIdx.x * WARPS_PER_B + wid;
    const uint16_t* xq = g_xh + q * 32;   // per-thread q offset folded in

    // prologue: first chunk's maps
    int cur_ir = 0, cur_or = 0;
    if (g < NCHUNKS) {
        const int gi0 = k * MPAIRS + g * 32 + lane;
        cur_ir = in_map[gi0];
        cur_or = out_map[gi0];
    }

    for (int c = g; c < NCHUNKS; c += STREAMS) {
        // prefetch next chunk's maps behind this chunk's MMA work
        int nxt_ir = 0, nxt_or = 0;
        const int nc = c + STREAMS;
        if (nc < NCHUNKS) {
            const int gin = k * MPAIRS + nc * 32 + lane;
            nxt_ir = in_map[gin];
            nxt_or = out_map[gin];
        }

        // Fragment row pointers: [ms][rowhalf]
        const uint16_t* pa[2][2];
        #pragma unroll
        for (int ms = 0; ms < 2; ms++) {
            const int rlo = __shfl_sync(0xffffffffu, cur_ir, ms * 16 + (lane >> 2));
            const int rhi = __shfl_sync(0xffffffffu, cur_ir, ms * 16 + 8 + (lane >> 2));
            pa[ms][0] = xq + (size_t)rlo * 128;
            pa[ms][1] = xq + (size_t)rhi * 128;
        }

        float acc[2][8][4];
        #pragma unroll
        for (int ms = 0; ms < 2; ms++)
            #pragma unroll
            for (int nt = 0; nt < 8; nt++)
                #pragma unroll
                for (int u = 0; u < 4; u++) acc[ms][nt][u] = 0.f;

        #pragma unroll
        for (int i = 0; i < 4; i++) {      // ks pairs: (2i, 2i+1)
            uint4 lo[2], hi[2];
            #pragma unroll
            for (int ms = 0; ms < 2; ms++) {
                lo[ms] = *(const uint4*)(pa[ms][0] + i * 8);
                hi[ms] = *(const uint4*)(pa[ms][1] + i * 8);
            }
            #pragma unroll
            for (int s = 0; s < 2; s++) {
                const int ks = 2 * i + s;
                uint32_t B[4][4];
                #pragma unroll
                for (int ng = 0; ng < 4; ng++)
                    ldmx4t(B[ng], bBase + ks * 16 * B_STRIDE + ng * 32);

                #pragma unroll
                for (int ms = 0; ms < 2; ms++) {
                    const uint32_t a0 = s ? lo[ms].z : lo[ms].x;
                    const uint32_t a2 = s ? lo[ms].w : lo[ms].y;
                    const uint32_t a1 = s ? hi[ms].z : hi[ms].x;
                    const uint32_t a3 = s ? hi[ms].w : hi[ms].y;
                    #pragma unroll
                    for (int nt = 0; nt < 8; nt++) {
                        const int ng = nt >> 1;
                        const int pp = (nt & 1) * 2;
                        mma_fp16(acc[ms][nt], a0, a1, a2, a3, B[ng][pp], B[ng][pp + 1]);
                    }
                }
            }
        }

        // ---- scatter-add ----
        #pragma unroll
        for (int ms = 0; ms < 2; ms++) {
            const int row0 = ms * 16 + (lane >> 2);
            const int or0 = __shfl_sync(0xffffffffu, cur_or, row0);
            const int or1 = __shfl_sync(0xffffffffu, cur_or, row0 + 8);
            float* d0 = out + (size_t)or0 * C_OUT + q * 2;
            float* d1 = out + (size_t)or1 * C_OUT + q * 2;
            #pragma unroll
            for (int nt = 0; nt < 8; nt++) {
                asm volatile("red.global.add.v2.f32 [%0], {%1, %2};"
                             :: "l"(d0 + nt * 8),
                                "f"(acc[ms][nt][0]), "f"(acc[ms][nt][1]) : "memory");
                asm volatile("red.global.add.v2.f32 [%0], {%1, %2};"
                             :: "l"(d1 + nt * 8),
                                "f"(acc[ms][nt][2]), "f"(acc[ms][nt][3]) : "memory");
            }
        }

        cur_ir = nxt_ir;
        cur_or = nxt_or;
    }
}

// ---------------------------------------------------------------------------
// Per-channel sum / sumsq over [N_OUT, 64]
// ---------------------------------------------------------------------------
__global__ void stats_kernel(const float* __restrict__ out) {
    const int c    = threadIdx.x & 63;
    const int rsub = threadIdx.x >> 6;
    float s = 0.f, q = 0.f;
    for (int r = blockIdx.x * 4 + rsub; r < N_OUT; r += gridDim.x * 4) {
        float v = out[(size_t)r * C_OUT + c];
        s += v;
        q = fmaf(v, v, q);
    }
    __shared__ float ssh[256];
    __shared__ float qsh[256];
    ssh[threadIdx.x] = s;
    qsh[threadIdx.x] = q;
    __syncthreads();
    if (rsub == 0) {
        s = ssh[c] + ssh[c + 64] + ssh[c + 128] + ssh[c + 192];
        q = qsh[c] + qsh[c + 64] + qsh[c + 128] + qsh[c + 192];
        atomicAdd(&g_sum[c], s);
        atomicAdd(&g_sq[c], q);
    }
}

// ---------------------------------------------------------------------------
// Normalize + ReLU with inline BN finalize
// ---------------------------------------------------------------------------
__global__ void norm_kernel(float* __restrict__ out,
                            const float* __restrict__ gamma,
                            const float* __restrict__ beta,
                            long long n4) {
    __shared__ float s_scale[C_OUT];
    __shared__ float s_bias[C_OUT];
    if (threadIdx.x < C_OUT) {
        const int c = threadIdx.x;
        const float invn = 1.0f / (float)N_OUT;
        float mean = g_sum[c] * invn;
        float var  = g_sq[c] * invn - mean * mean;
        float sc   = gamma[c] * rsqrtf(var + BN_EPS);
        s_scale[c] = sc;
        s_bias[c]  = beta[c] - mean * sc;
    }
    __syncthreads();
    long long i = (long long)blockIdx.x * blockDim.x + threadIdx.x;
    if (i < n4) {
        float4 v = ((float4*)out)[i];
        int c0 = (int)((i * 4) & 63);
        v.x = fmaxf(fmaf(v.x, s_scale[c0 + 0], s_bias[c0 + 0]), 0.f);
        v.y = fmaxf(fmaf(v.y, s_scale[c0 + 1], s_bias[c0 + 1]), 0.f);
        v.z = fmaxf(fmaf(v.z, s_scale[c0 + 2], s_bias[c0 + 2]), 0.f);
        v.w = fmaxf(fmaf(v.w, s_scale[c0 + 3], s_bias[c0 + 3]), 0.f);
        ((float4*)out)[i] = v;
    }
}

// ---------------------------------------------------------------------------
// kernel_launch — graph-capturable, default stream
// Inputs (metadata order): x, weight, gamma, beta, in_map, out_map
// ---------------------------------------------------------------------------
extern "C" void kernel_launch(void* const* d_in, const int* in_sizes, int n_in,
                              void* d_out, int out_size)
{
    const float* x       = (const float*)d_in[0];
    const float* weight  = (const float*)d_in[1];
    const float* gamma   = (const float*)d_in[2];
    const float* beta    = (const float*)d_in[3];
    const int*   in_map  = (const int*)d_in[4];
    const int*   out_map = (const int*)d_in[5];
    float*       out     = (float*)d_out;

    cudaMemsetAsync(out, 0, (size_t)out_size * sizeof(float));

    prep_kernel<<<(N_IN * 32 + 255) / 256, 256>>>(x);

    dim3 cgrid(BLOCKS_X, KOFF);
    conv_mma_kernel<<<cgrid, 128, SMEM_TOTAL>>>(weight, in_map, out_map, out);

    stats_kernel<<<592, 256>>>(out);

    long long n4 = (long long)out_size / 4;
    norm_kernel<<<(int)((n4 + 255) / 256), 256>>>(out, gamma, beta, n4);
}